// round 13
// baseline (speedup 1.0000x reference)
#include <cuda_runtime.h>
#include <cuda_bf16.h>
#include <cstdint>

#define N_IN       16
#define FANIN      16
#define N_NODES    512
#define N_OUT      64
#define BATCH      32768
#define OUT_START  (N_NODES - N_OUT)    // node 448

#define THREADS    256
#define GRID       (BATCH / THREADS)    // 128 CTAs, 8 warps/SM = 2/SMSP

#define PAD_NODES  (N_NODES + 2)        // rows 512,513 readable (zero)

using u32 = unsigned int;

// Full raw weight rows in the constant bank; only taps 8..15 (float4 #2,#3 of
// each row) are read from here — 2x LDC.128 per node (const-port floor 32
// cyc/SMSP/node, well under the issue floor). Zero-initialized pad rows.
__constant__ float4 cW4[PAD_NODES * 4] = {};

__device__ __forceinline__ float tanh_approx(float x) {
    float y; asm("tanh.approx.f32 %0, %1;" : "=f"(y) : "f"(x)); return y;
}
__device__ __forceinline__ u32 smem_u32(const void* p) {
    u32 a;
    asm("{ .reg .u64 t; cvta.to.shared.u64 t, %1; cvt.u32.u64 %0, t; }"
        : "=r"(a) : "l"(p));
    return a;
}
// volatile: prefetches must stay where placed (consumed next iteration)
__device__ __forceinline__ void lds_v4(float4& d, u32 addr) {
    asm volatile("ld.shared.v4.f32 {%0,%1,%2,%3}, [%4];"
                 : "=f"(d.x), "=f"(d.y), "=f"(d.z), "=f"(d.w) : "r"(addr));
}
__device__ __forceinline__ void lds_v2(float2& d, u32 addr) {
    asm volatile("ld.shared.v2.f32 {%0,%1}, [%2];"
                 : "=f"(d.x), "=f"(d.y) : "r"(addr));
}

__global__ void __launch_bounds__(THREADS, 1)
neat_forward_split2(const float* __restrict__ x,
                    const float* __restrict__ w,      // [512][16] raw
                    const float* __restrict__ bias,   // [512]
                    const float* __restrict__ resp,   // [512]
                    float*       __restrict__ out)    // [BATCH][64]
{
    // smem: taps 0..7 per node (raw), and {bias, resp} pairs
    __shared__ __align__(16) float  sh_lo[PAD_NODES * 8];   // ~16.4 KB
    __shared__ __align__(8)  float2 sh_br[PAD_NODES];       // ~4.1 KB

    const int tid = threadIdx.x;

    {   // taps 0..7 = first two float4s of each 16-float row
        const float4* w4 = (const float4*)w;
        float4* lo4 = (float4*)sh_lo;
        for (int i = tid; i < N_NODES * 2; i += THREADS)
            lo4[i] = w4[(i >> 1) * 4 + (i & 1)];
        if (tid < 4) lo4[N_NODES * 2 + tid] = make_float4(0.f, 0.f, 0.f, 0.f);
        for (int i = tid; i < N_NODES; i += THREADS)
            sh_br[i] = make_float2(bias[i], resp[i]);
        if (tid < 2) sh_br[N_NODES + tid] = make_float2(0.f, 0.f);
    }
    __syncthreads();

    const int b = blockIdx.x * THREADS + tid;   // one batch element per thread

    // Circular window: v[g & 15] = TRUE node value at global index g
    // (inputs raw; compute nodes tanh(.)*resp). Matches reference gather.
    float v[16];
    {
        const float4* xv = (const float4*)(x + (size_t)b * N_IN);
        #pragma unroll
        for (int q = 0; q < 4; q++) {
            float4 t = xv[q];
            v[4*q+0] = t.x; v[4*q+1] = t.y; v[4*q+2] = t.z; v[4*q+3] = t.w;
        }
    }

    float* outp = out + (size_t)b * N_OUT;
    const u32 lobase = smem_u32(sh_lo);         // row stride 32 B
    const u32 brbase = smem_u32(sh_br);         // stride 8 B

    // ---- Pipeline prologue ----
    // pp   : partial of node 0 (taps 0..14 + bias); w15c, rc for node 0
    float pp, w15c, rc;
    {
        float b0 = fmaf(v[0], w[0], bias[0]);
        float b1 = v[1] * w[1];
        float b2 = v[2] * w[2];
        float b3 = v[3] * w[3];
        #pragma unroll
        for (int t = 4; t < 12; t += 4) {
            b0 = fmaf(v[t + 0], w[t + 0], b0);
            b1 = fmaf(v[t + 1], w[t + 1], b1);
            b2 = fmaf(v[t + 2], w[t + 2], b2);
            b3 = fmaf(v[t + 3], w[t + 3], b3);
        }
        b0 = fmaf(v[12], w[12], b0);
        b1 = fmaf(v[13], w[13], b1);
        b2 = fmaf(v[14], w[14], b2);
        pp = (b0 + b1) + (b2 + b3);
        w15c = w[15];
        rc = resp[0];
    }
    // row 1 operands (consumed in iteration j=0's C block)
    float4 cq0, cq1, ch0, ch1; float2 cbr;
    {
        const float4* lo4 = (const float4*)sh_lo;
        cq0 = lo4[2]; cq1 = lo4[3];             // row 1 taps 0..7
        ch0 = cW4[1 * 4 + 2]; ch1 = cW4[1 * 4 + 3];  // row 1 taps 8..15
        cbr = sh_br[1];
    }

    float4 ob;                                  // output staging

    #pragma unroll 1
    for (int g = 0; g < N_NODES / 16; g++) {
        #pragma unroll
        for (int j = 0; j < 16; j++) {
            const int node = g * 16 + j;

            // ---- A: serial path: fma + tanh + resp-mul ----
            const float yl  = v[(j + 15) & 15];          // value of global node+15
            const float y   = tanh_approx(fmaf(yl, w15c, pp)) * rc;
            v[j] = y;                                    // global node+16

            if (node >= OUT_START) {
                const int o = node - OUT_START;
                if ((j & 3) == 0) ob.x = y;
                if ((j & 3) == 1) ob.y = y;
                if ((j & 3) == 2) ob.z = y;
                if ((j & 3) == 3) { ob.w = y; *(float4*)(outp + (o - 3)) = ob; }
            }

            // ---- B: prefetch row node+2 (smem volatile + const) ----
            float4 nq0, nq1;
            const u32 ra = lobase + (u32)(node + 2) * 32;
            lds_v4(nq0, ra);
            lds_v4(nq1, ra + 16);
            float2 nbr;
            lds_v2(nbr, brbase + (u32)(node + 2) * 8);
            const float4 nh0 = cW4[(node + 2) * 4 + 2];
            const float4 nh1 = cW4[(node + 2) * 4 + 3];

            // ---- C: 15-tap partial for node+1 from row loaded LAST iter ----
            // taps t=0..14 -> globals node+1 .. node+15 (slot j excluded).
            float b0 = fmaf(v[(j + 1)  & 15], cq0.x, cbr.x);
            float b1 =      v[(j + 2)  & 15] * cq0.y;
            float b2 =      v[(j + 3)  & 15] * cq0.z;
            float b3 =      v[(j + 4)  & 15] * cq0.w;
            b0 = fmaf(v[(j + 5)  & 15], cq1.x, b0);
            b1 = fmaf(v[(j + 6)  & 15], cq1.y, b1);
            b2 = fmaf(v[(j + 7)  & 15], cq1.z, b2);
            b3 = fmaf(v[(j + 8)  & 15], cq1.w, b3);
            b0 = fmaf(v[(j + 9)  & 15], ch0.x, b0);
            b1 = fmaf(v[(j + 10) & 15], ch0.y, b1);
            b2 = fmaf(v[(j + 11) & 15], ch0.z, b2);
            b3 = fmaf(v[(j + 12) & 15], ch0.w, b3);
            b0 = fmaf(v[(j + 13) & 15], ch1.x, b0);
            b1 = fmaf(v[(j + 14) & 15], ch1.y, b1);
            b2 = fmaf(v[(j + 15) & 15], ch1.z, b2);      // tap14 (newest) late
            pp   = (b0 + b1) + (b2 + b3);
            w15c = ch1.w;
            rc   = cbr.y;                                // resp of node+1

            // ---- rotate row pipeline ----
            cq0 = nq0; cq1 = nq1; ch0 = nh0; ch1 = nh1; cbr = nbr;
        }
    }
}

extern "C" void kernel_launch(void* const* d_in, const int* in_sizes, int n_in,
                              void* d_out, int out_size) {
    const float* x    = (const float*)d_in[0];   // [BATCH, 16]
    const float* w    = (const float*)d_in[1];   // [512, 16]
    const float* bias = (const float*)d_in[2];   // [512]
    const float* resp = (const float*)d_in[3];   // [512]
    // d_in[4] (src_idx) is the fixed sliding-window topology; baked into indexing.
    float* out = (float*)d_out;                  // [BATCH, 64]

    // Raw weight rows -> constant bank (flat copy, graph-capturable).
    cudaMemcpyToSymbolAsync(cW4, w, N_NODES * FANIN * sizeof(float), 0,
                            cudaMemcpyDeviceToDevice, 0);

    neat_forward_split2<<<GRID, THREADS>>>(x, w, bias, resp, out);
}

// round 14
// speedup vs baseline: 1.8918x; 1.8918x over previous
#include <cuda_runtime.h>
#include <cuda_bf16.h>
#include <cstdint>

#define N_IN       16
#define FANIN      16
#define N_NODES    512
#define N_OUT      64
#define BATCH      32768
#define HALF       (BATCH / 2)          // 16384
#define OUT_START  (N_NODES - N_OUT)    // node 448

#define THREADS    128
#define GRID       (HALF / THREADS)     // 128 CTAs, 4 warps/SM = 1/SMSP

#define PAD_NODES  (N_NODES + 2)        // rows 512,513 zero (lookahead tail)

using u32 = unsigned int;

__constant__ float cB[PAD_NODES] = {};  // bias (zero-padded): scalar LDC is cheap
__constant__ float cR[N_OUT]     = {};  // response of output nodes

__device__ __forceinline__ float tanh_approx(float x) {
    float y; asm("tanh.approx.f32 %0, %1;" : "=f"(y) : "f"(x)); return y;
}
__device__ __forceinline__ u32 smem_u32(const void* p) {
    u32 a;
    asm("{ .reg .u64 t; cvta.to.shared.u64 t, %1; cvt.u32.u64 %0, t; }"
        : "=r"(a) : "l"(p));
    return a;
}
// volatile: row prefetch must stay where placed (consumed next iteration)
__device__ __forceinline__ void lds_v4(float4& d, u32 addr) {
    asm volatile("ld.shared.v4.f32 {%0,%1,%2,%3}, [%4];"
                 : "=f"(d.x), "=f"(d.y), "=f"(d.z), "=f"(d.w) : "r"(addr));
}

__global__ void __launch_bounds__(THREADS, 1)
neat_forward_rp2(const float* __restrict__ x,
                 const float* __restrict__ w,      // [512][16]
                 const float* __restrict__ resp,   // [512]
                 float*       __restrict__ out)    // [BATCH][64]
{
    __shared__ __align__(16) float sh_w[PAD_NODES * FANIN];   // ~32.9 KB

    const int tid = threadIdx.x;

    // Fold source responses into consumer weights:
    //   w'[i][t] = w[i][t] * resp[i + t - 16]  (identity for input sources).
    // Windows carry RAW tanh values; resp applied only at output stores.
    for (int i = tid; i < N_NODES * FANIN; i += THREADS) {
        const int node = i >> 4, t = i & 15;
        const int g = node + t;
        const float s = (g >= N_IN) ? resp[g - N_IN] : 1.0f;
        sh_w[i] = w[i] * s;
    }
    for (int i = tid; i < 2 * FANIN; i += THREADS)
        sh_w[N_NODES * FANIN + i] = 0.0f;                      // pad rows
    __syncthreads();

    // Two chains per thread share one weight-load stream.
    const int b0 = blockIdx.x * THREADS + tid;
    const int b1 = b0 + HALF;

    // Circular windows: v*[g & 15] = value at global index g.
    float vA[16], vB[16];
    {
        const float4* x0 = (const float4*)(x + (size_t)b0 * N_IN);
        const float4* x1 = (const float4*)(x + (size_t)b1 * N_IN);
        #pragma unroll
        for (int q = 0; q < 4; q++) {
            float4 t0 = x0[q], t1 = x1[q];
            vA[4*q+0] = t0.x; vA[4*q+1] = t0.y; vA[4*q+2] = t0.z; vA[4*q+3] = t0.w;
            vB[4*q+0] = t1.x; vB[4*q+1] = t1.y; vB[4*q+2] = t1.z; vB[4*q+3] = t1.w;
        }
    }

    float* outp0 = out + (size_t)b0 * N_OUT;
    float* outp1 = out + (size_t)b1 * N_OUT;
    const u32 wbase = smem_u32(sh_w);           // row stride 64 B

    // ---- Pipeline prologue ----
    // pp*  : partial of node 0 (taps 0..14 + bias), w15c = w'[0][15]
    // cq*  : weight row of node 1 (consumed in iteration j=0's C block)
    float ppA, ppB, w15c;
    {
        const float* r0 = sh_w;
        float a0 = fmaf(vA[0], r0[0], cB[0]);
        float a1 = vA[1] * r0[1];
        float c0 = fmaf(vB[0], r0[0], cB[0]);
        float c1 = vB[1] * r0[1];
        #pragma unroll
        for (int t = 2; t < 14; t += 2) {
            a0 = fmaf(vA[t],     r0[t],     a0);
            a1 = fmaf(vA[t + 1], r0[t + 1], a1);
            c0 = fmaf(vB[t],     r0[t],     c0);
            c1 = fmaf(vB[t + 1], r0[t + 1], c1);
        }
        a0 = fmaf(vA[14], r0[14], a0);
        c0 = fmaf(vB[14], r0[14], c0);
        ppA = a0 + a1;
        ppB = c0 + c1;
        w15c = r0[15];
    }
    float4 cq0, cq1, cq2, cq3;                  // row of node 1
    {
        const float4* r1 = (const float4*)(sh_w + FANIN);
        cq0 = r1[0]; cq1 = r1[1]; cq2 = r1[2]; cq3 = r1[3];
    }

    float4 obA, obB;                            // output staging (float4 stores)

    #pragma unroll 1
    for (int g = 0; g < N_NODES / 16; g++) {
        #pragma unroll
        for (int j = 0; j < 16; j++) {
            const int node = g * 16 + j;

            // ---- A: serial paths (independent across chains): fma + tanh ---
            const float ylA = vA[(j + 15) & 15];        // y_{node-1}
            const float ylB = vB[(j + 15) & 15];
            const float yA = tanh_approx(fmaf(ylA, w15c, ppA));
            const float yB = tanh_approx(fmaf(ylB, w15c, ppB));
            vA[j] = yA;
            vB[j] = yB;

            if (node >= OUT_START) {
                const int o = node - OUT_START;
                const float r = cR[o];
                const float oA = yA * r, oB = yB * r;
                if ((j & 3) == 0) { obA.x = oA; obB.x = oB; }
                if ((j & 3) == 1) { obA.y = oA; obB.y = oB; }
                if ((j & 3) == 2) { obA.z = oA; obB.z = oB; }
                if ((j & 3) == 3) {
                    obA.w = oA; obB.w = oB;
                    *(float4*)(outp0 + (o - 3)) = obA;
                    *(float4*)(outp1 + (o - 3)) = obB;
                }
            }

            // ---- B: prefetch weight row node+2 (volatile, used at j+1) -----
            float4 nq0, nq1, nq2, nq3;
            const u32 ra = wbase + (u32)(node + 2) * 64;
            lds_v4(nq0, ra);
            lds_v4(nq1, ra + 16);
            lds_v4(nq2, ra + 32);
            lds_v4(nq3, ra + 48);

            // ---- C: 15-tap partials for node+1 from row loaded LAST iter ---
            // taps t=0..14 -> globals node+1 .. node+15 (slot j excluded).
            const float bb = cB[node + 1];
            float a0 = fmaf(vA[(j + 1)  & 15], cq0.x, bb);
            float a1 =      vA[(j + 2)  & 15] * cq0.y;
            float c0 = fmaf(vB[(j + 1)  & 15], cq0.x, bb);
            float c1 =      vB[(j + 2)  & 15] * cq0.y;
            a0 = fmaf(vA[(j + 3)  & 15], cq0.z, a0);
            a1 = fmaf(vA[(j + 4)  & 15], cq0.w, a1);
            c0 = fmaf(vB[(j + 3)  & 15], cq0.z, c0);
            c1 = fmaf(vB[(j + 4)  & 15], cq0.w, c1);
            a0 = fmaf(vA[(j + 5)  & 15], cq1.x, a0);
            a1 = fmaf(vA[(j + 6)  & 15], cq1.y, a1);
            c0 = fmaf(vB[(j + 5)  & 15], cq1.x, c0);
            c1 = fmaf(vB[(j + 6)  & 15], cq1.y, c1);
            a0 = fmaf(vA[(j + 7)  & 15], cq1.z, a0);
            a1 = fmaf(vA[(j + 8)  & 15], cq1.w, a1);
            c0 = fmaf(vB[(j + 7)  & 15], cq1.z, c0);
            c1 = fmaf(vB[(j + 8)  & 15], cq1.w, c1);
            a0 = fmaf(vA[(j + 9)  & 15], cq2.x, a0);
            a1 = fmaf(vA[(j + 10) & 15], cq2.y, a1);
            c0 = fmaf(vB[(j + 9)  & 15], cq2.x, c0);
            c1 = fmaf(vB[(j + 10) & 15], cq2.y, c1);
            a0 = fmaf(vA[(j + 11) & 15], cq2.z, a0);
            a1 = fmaf(vA[(j + 12) & 15], cq2.w, a1);
            c0 = fmaf(vB[(j + 11) & 15], cq2.z, c0);
            c1 = fmaf(vB[(j + 12) & 15], cq2.w, c1);
            a0 = fmaf(vA[(j + 13) & 15], cq3.x, a0);
            a1 = fmaf(vA[(j + 14) & 15], cq3.y, a1);
            c0 = fmaf(vB[(j + 13) & 15], cq3.x, c0);
            c1 = fmaf(vB[(j + 14) & 15], cq3.y, c1);
            a0 = fmaf(vA[(j + 15) & 15], cq3.z, a0);    // tap14 (newest) late
            c0 = fmaf(vB[(j + 15) & 15], cq3.z, c0);
            ppA  = a0 + a1;
            ppB  = c0 + c1;
            w15c = cq3.w;

            // ---- rotate row pipeline ----
            cq0 = nq0; cq1 = nq1; cq2 = nq2; cq3 = nq3;
        }
    }
}

extern "C" void kernel_launch(void* const* d_in, const int* in_sizes, int n_in,
                              void* d_out, int out_size) {
    const float* x    = (const float*)d_in[0];   // [BATCH, 16]
    const float* w    = (const float*)d_in[1];   // [512, 16]
    const float* bias = (const float*)d_in[2];   // [512]
    const float* resp = (const float*)d_in[3];   // [512]
    // d_in[4] (src_idx) is the fixed sliding-window topology; baked into indexing.
    float* out = (float*)d_out;                  // [BATCH, 64]

    cudaMemcpyToSymbolAsync(cB, bias, N_NODES * sizeof(float), 0,
                            cudaMemcpyDeviceToDevice, 0);
    cudaMemcpyToSymbolAsync(cR, resp + OUT_START, N_OUT * sizeof(float), 0,
                            cudaMemcpyDeviceToDevice, 0);

    neat_forward_rp2<<<GRID, THREADS>>>(x, w, resp, out);
}

// round 15
// speedup vs baseline: 2.0560x; 1.0868x over previous
#include <cuda_runtime.h>
#include <cuda_bf16.h>
#include <cstdint>

#define N_IN       16
#define FANIN      16
#define N_NODES    512
#define N_OUT      64
#define BATCH      32768
#define HALF       (BATCH / 2)          // 16384
#define OUT_START  (N_NODES - N_OUT)    // node 448

#define THREADS    128
#define GRID       (HALF / THREADS)     // 128 CTAs, 4 warps/SM = 1/SMSP

#define PAD_NODES  (N_NODES + 2)        // rows 512,513 zero (lookahead tail)

using u32 = unsigned int;
using u64 = unsigned long long;

__constant__ float cB[PAD_NODES] = {};  // bias (zero-padded)
__constant__ float cR[N_OUT]     = {};  // response of output nodes

__device__ __forceinline__ float tanh_approx(float x) {
    float y; asm("tanh.approx.f32 %0, %1;" : "=f"(y) : "f"(x)); return y;
}
__device__ __forceinline__ u32 smem_u32(const void* p) {
    u32 a;
    asm("{ .reg .u64 t; cvta.to.shared.u64 t, %1; cvt.u32.u64 %0, t; }"
        : "=r"(a) : "l"(p));
    return a;
}
__device__ __forceinline__ void lds_v4(float4& d, u32 addr) {
    asm volatile("ld.shared.v4.f32 {%0,%1,%2,%3}, [%4];"
                 : "=f"(d.x), "=f"(d.y), "=f"(d.z), "=f"(d.w) : "r"(addr));
}
// ---- packed f32x2 helpers ----
__device__ __forceinline__ u64 pack2(float lo, float hi) {
    u64 r; asm("mov.b64 %0, {%1, %2};" : "=l"(r) : "f"(lo), "f"(hi)); return r;
}
__device__ __forceinline__ u64 dup2(float v) {            // {v, v} on ALU pipe
    u64 r; asm("mov.b64 %0, {%1, %1};" : "=l"(r) : "f"(v)); return r;
}
__device__ __forceinline__ void unpack2(u64 v, float& lo, float& hi) {
    asm("mov.b64 {%0, %1}, %2;" : "=f"(lo), "=f"(hi) : "l"(v));
}
__device__ __forceinline__ u64 fma2(u64 a, u64 b, u64 c) {
    u64 d; asm("fma.rn.f32x2 %0, %1, %2, %3;" : "=l"(d) : "l"(a), "l"(b), "l"(c)); return d;
}
__device__ __forceinline__ u64 add2(u64 a, u64 b) {
    u64 d; asm("add.rn.f32x2 %0, %1, %2;" : "=l"(d) : "l"(a), "l"(b)); return d;
}

__global__ void __launch_bounds__(THREADS, 1)
neat_forward_rp2x2(const float* __restrict__ x,
                   const float* __restrict__ w,      // [512][16]
                   const float* __restrict__ resp,   // [512]
                   float*       __restrict__ out)    // [BATCH][64]
{
    __shared__ __align__(16) float sh_w[PAD_NODES * FANIN];   // ~32.9 KB

    const int tid = threadIdx.x;

    // Fold source responses into consumer weights:
    //   w'[i][t] = w[i][t] * resp[i + t - 16]  (identity for input sources).
    // Window carries RAW tanh values (packed pairs); resp applied at stores.
    for (int i = tid; i < N_NODES * FANIN; i += THREADS) {
        const int node = i >> 4, t = i & 15;
        const int g = node + t;
        const float s = (g >= N_IN) ? resp[g - N_IN] : 1.0f;
        sh_w[i] = w[i] * s;
    }
    for (int i = tid; i < 2 * FANIN; i += THREADS)
        sh_w[N_NODES * FANIN + i] = 0.0f;                      // pad rows
    __syncthreads();

    // One packed pair per thread: batch elements (b0, b0 + HALF).
    const int b0 = blockIdx.x * THREADS + tid;
    const int b1 = b0 + HALF;

    // Packed circular window: v2[g & 15] = {val_b0, val_b1} at global index g.
    u64 v2[16];
    {
        const float4* x0 = (const float4*)(x + (size_t)b0 * N_IN);
        const float4* x1 = (const float4*)(x + (size_t)b1 * N_IN);
        #pragma unroll
        for (int q = 0; q < 4; q++) {
            float4 t0 = x0[q], t1 = x1[q];
            v2[4*q+0] = pack2(t0.x, t1.x);
            v2[4*q+1] = pack2(t0.y, t1.y);
            v2[4*q+2] = pack2(t0.z, t1.z);
            v2[4*q+3] = pack2(t0.w, t1.w);
        }
    }

    float* outp0 = out + (size_t)b0 * N_OUT;
    float* outp1 = out + (size_t)b1 * N_OUT;
    const u32 wbase = smem_u32(sh_w);           // row stride 64 B

    // ---- Pipeline prologue ----
    // pp2   : packed partial of node 0 (taps 0..14 + bias); w15c2 for node 0
    // cq*   : scalar weight row of node 1 (consumed in iteration j=0's C)
    u64 pp2, w15c2;
    {
        const float* r0 = sh_w;
        u64 a0 = fma2(v2[0], dup2(r0[0]), dup2(cB[0]));
        u64 a1 = fma2(v2[1], dup2(r0[1]), pack2(0.f, 0.f));
        #pragma unroll
        for (int t = 2; t < 14; t += 2) {
            a0 = fma2(v2[t],     dup2(r0[t]),     a0);
            a1 = fma2(v2[t + 1], dup2(r0[t + 1]), a1);
        }
        a0 = fma2(v2[14], dup2(r0[14]), a0);
        pp2 = add2(a0, a1);
        w15c2 = dup2(r0[15]);
    }
    float4 cq0, cq1, cq2, cq3;                  // row of node 1
    {
        const float4* r1 = (const float4*)(sh_w + FANIN);
        cq0 = r1[0]; cq1 = r1[1]; cq2 = r1[2]; cq3 = r1[3];
    }

    float4 obA, obB;                            // output staging

    #pragma unroll 1
    for (int g = 0; g < N_NODES / 16; g++) {
        #pragma unroll
        for (int j = 0; j < 16; j++) {
            const int node = g * 16 + j;

            // ---- A: serial path (packed fma -> 2x tanh -> pack) ----
            const u64 yl2  = v2[(j + 15) & 15];         // y_{node-1} pair
            const u64 agg2 = fma2(yl2, w15c2, pp2);
            float aA, aB;
            unpack2(agg2, aA, aB);
            const float yA = tanh_approx(aA);
            const float yB = tanh_approx(aB);
            v2[j] = pack2(yA, yB);

            if (node >= OUT_START) {
                const int o = node - OUT_START;
                const float r = cR[o];
                const float oA = yA * r, oB = yB * r;
                if ((j & 3) == 0) { obA.x = oA; obB.x = oB; }
                if ((j & 3) == 1) { obA.y = oA; obB.y = oB; }
                if ((j & 3) == 2) { obA.z = oA; obB.z = oB; }
                if ((j & 3) == 3) {
                    obA.w = oA; obB.w = oB;
                    *(float4*)(outp0 + (o - 3)) = obA;
                    *(float4*)(outp1 + (o - 3)) = obB;
                }
            }

            // ---- B: prefetch weight row node+2 (volatile, used at j+1) ----
            float4 nq0, nq1, nq2, nq3;
            const u32 ra = wbase + (u32)(node + 2) * 64;
            lds_v4(nq0, ra);
            lds_v4(nq1, ra + 16);
            lds_v4(nq2, ra + 32);
            lds_v4(nq3, ra + 48);

            // ---- C: packed 15-tap partial for node+1 from LAST iter's row --
            // taps t=0..14 -> globals node+1 .. node+15 (slot j excluded).
            // dup2 movs ride the (idle) ALU pipe; fma2 halves fma-pipe load.
            u64 a0 = fma2(v2[(j + 1)  & 15], dup2(cq0.x), dup2(cB[node + 1]));
            u64 a1 = fma2(v2[(j + 2)  & 15], dup2(cq0.y), pack2(0.f, 0.f));
            a0 = fma2(v2[(j + 3)  & 15], dup2(cq0.z), a0);
            a1 = fma2(v2[(j + 4)  & 15], dup2(cq0.w), a1);
            a0 = fma2(v2[(j + 5)  & 15], dup2(cq1.x), a0);
            a1 = fma2(v2[(j + 6)  & 15], dup2(cq1.y), a1);
            a0 = fma2(v2[(j + 7)  & 15], dup2(cq1.z), a0);
            a1 = fma2(v2[(j + 8)  & 15], dup2(cq1.w), a1);
            a0 = fma2(v2[(j + 9)  & 15], dup2(cq2.x), a0);
            a1 = fma2(v2[(j + 10) & 15], dup2(cq2.y), a1);
            a0 = fma2(v2[(j + 11) & 15], dup2(cq2.z), a0);
            a1 = fma2(v2[(j + 12) & 15], dup2(cq2.w), a1);
            a0 = fma2(v2[(j + 13) & 15], dup2(cq3.x), a0);
            a1 = fma2(v2[(j + 14) & 15], dup2(cq3.y), a1);
            a0 = fma2(v2[(j + 15) & 15], dup2(cq3.z), a0);   // tap14 (newest) late
            pp2   = add2(a0, a1);
            w15c2 = dup2(cq3.w);

            // ---- rotate row pipeline ----
            cq0 = nq0; cq1 = nq1; cq2 = nq2; cq3 = nq3;
        }
    }
}

extern "C" void kernel_launch(void* const* d_in, const int* in_sizes, int n_in,
                              void* d_out, int out_size) {
    const float* x    = (const float*)d_in[0];   // [BATCH, 16]
    const float* w    = (const float*)d_in[1];   // [512, 16]
    const float* bias = (const float*)d_in[2];   // [512]
    const float* resp = (const float*)d_in[3];   // [512]
    // d_in[4] (src_idx) is the fixed sliding-window topology; baked into indexing.
    float* out = (float*)d_out;                  // [BATCH, 64]

    cudaMemcpyToSymbolAsync(cB, bias, N_NODES * sizeof(float), 0,
                            cudaMemcpyDeviceToDevice, 0);
    cudaMemcpyToSymbolAsync(cR, resp + OUT_START, N_OUT * sizeof(float), 0,
                            cudaMemcpyDeviceToDevice, 0);

    neat_forward_rp2x2<<<GRID, THREADS>>>(x, w, resp, out);
}